// round 12
// baseline (speedup 1.0000x reference)
#include <cuda_runtime.h>
#include <cstdint>

// Problem constants
#define B_  4
#define S_  2048
#define E_  512
#define Q_  8
#define F_  2048
#define M_  (B_ * S_)

// Tiling (round-9/11 best config)
#define BM 64
#define BN 256
#define BK 32
#define NTH 256
#define NCHUNK (F_ / BK)      // 64

// SMEM (floats): only B double buffer now
#define BCH_F   8192          // 32 KB per chunk, fragment/lane-ordered
#define SMEM_TOTAL_BYTES (2 * BCH_F * 4)   // 65536 B

// ---- persistent scratch ----
// W2 permuted into lane-major B-fragment order, tf32-pre-rounded (as round 9/11):
//   [c (64)][n0blk (2)][ float4s: ((wnb*4 + ks)*4 + f)*32 + lane ][elem]
__device__ float g_W2P[(size_t)F_ * E_];
// H = relu(z@W1 + b1), tf32-rounded, in A-fragment lane-major order:
//   float4 index: ((m32blk*64 + c)*8 + ks*2 + mt)*32 + lane
//   where float4 = (A[r0][kt], A[r0+8][kt], A[r0][kt+4], A[r0+8][kt+4]),
//   r0 = m32blk*32 + mt*16 + (lane>>2), kt = c*32 + ks*8 + (lane&3)
__device__ float g_HP[(size_t)M_ * F_];    // 67 MB

// ---------------- helpers ----------------
__device__ __forceinline__ uint32_t smem_u32(const void* p) {
    uint32_t a;
    asm("{ .reg .u64 t; cvta.to.shared.u64 t, %1; cvt.u32.u64 %0, t; }" : "=r"(a) : "l"(p));
    return a;
}
__device__ __forceinline__ float to_tf32(float f) {
    uint32_t r;
    asm("cvt.rna.tf32.f32 %0, %1;" : "=r"(r) : "f"(f));
    return __uint_as_float(r);
}
__device__ __forceinline__ void cp16(uint32_t dst, const void* src) {
    asm volatile("cp.async.cg.shared.global [%0], [%1], 16;" :: "r"(dst), "l"(src));
}
#define CP_COMMIT() asm volatile("cp.async.commit_group;" ::: "memory")
#define CP_WAIT0()  asm volatile("cp.async.wait_group 0;" ::: "memory")

// D(16x8,f32) += A(16x8,tf32 row) * B(8x8,tf32 col)
__device__ __forceinline__ void mma8(float* d, const uint32_t* a, const uint32_t* b) {
    asm volatile(
        "mma.sync.aligned.m16n8k8.row.col.f32.tf32.tf32.f32 "
        "{%0,%1,%2,%3}, {%4,%5,%6,%7}, {%8,%9}, {%0,%1,%2,%3};"
        : "+f"(d[0]), "+f"(d[1]), "+f"(d[2]), "+f"(d[3])
        : "r"(a[0]), "r"(a[1]), "r"(a[2]), "r"(a[3]), "r"(b[0]), "r"(b[1]));
}

// ---------------- prepass 1: permute + tf32-round W2 into g_W2P ----------------
__global__ void w2_permute_kernel(const float* __restrict__ W2) {
    const int idx = blockIdx.x * 256 + threadIdx.x;     // 0 .. F_*E_-1
    const int k = idx >> 9;
    const int n = idx & (E_ - 1);

    const int c   = k >> 5;
    const int kk  = k & 31;
    const int ks  = kk >> 3;
    const int r8  = kk & 7;
    const int t   = r8 & 3;
    const int rh  = r8 >> 2;

    const int n0blk = n >> 8;
    const int n256  = n & 255;
    const int wnb   = n256 >> 6;
    const int n64   = n256 & 63;
    const int g     = n64 & 7;
    const int nt    = n64 >> 3;

    const int f    = rh * 2 + (nt >> 2);
    const int elem = nt & 3;
    const int lane = g * 4 + t;

    const size_t f4idx = (size_t)(((wnb * 4 + ks) * 4 + f) * 32 + lane);
    const size_t dst = ((size_t)c * 2 + n0blk) * BCH_F + f4idx * 4 + elem;
    g_W2P[dst] = to_tf32(W2[(size_t)k * E_ + n]);
}

// ---------------- prepass 2: compute H + permute into g_HP ----------------
// grid (M_/64, F_/128), block 256. Tile: 64 rows x 128 k.
__global__ __launch_bounds__(256) void h_permute_kernel(
    const float* __restrict__ x, const float* __restrict__ theta,
    const float* __restrict__ W1, const float* __restrict__ b1) {
    __shared__ float hs[64 * 132];     // stride 132: STS.128 + scalar reads conflict-free
    const int tid = threadIdx.x;
    const int m0  = blockIdx.x * 64;
    const int k0  = blockIdx.y * 128;
    const int hm  = tid & 63;
    const int kq  = tid >> 6;          // 0..3, k-span kq*32..+32 of the tile

    // z[q] = cos(theta[q]) * cos(x[m0+hm, q])
    float zreg[Q_];
    {
        const float4 x0 = *(const float4*)(x + (size_t)(m0 + hm) * E_);
        const float4 x1 = *(const float4*)(x + (size_t)(m0 + hm) * E_ + 4);
        zreg[0] = cosf(theta[0]) * cosf(x0.x);
        zreg[1] = cosf(theta[1]) * cosf(x0.y);
        zreg[2] = cosf(theta[2]) * cosf(x0.z);
        zreg[3] = cosf(theta[3]) * cosf(x0.w);
        zreg[4] = cosf(theta[4]) * cosf(x1.x);
        zreg[5] = cosf(theta[5]) * cosf(x1.y);
        zreg[6] = cosf(theta[6]) * cosf(x1.z);
        zreg[7] = cosf(theta[7]) * cosf(x1.w);
    }

    #pragma unroll
    for (int c2 = 0; c2 < 8; c2++) {
        const int kk = kq * 32 + c2 * 4;
        const float4 b1v = *(const float4*)(b1 + k0 + kk);
        float h0 = b1v.x, h1 = b1v.y, h2 = b1v.z, h3 = b1v.w;
        #pragma unroll
        for (int q = 0; q < Q_; q++) {
            const float4 wv = *(const float4*)(W1 + (size_t)q * F_ + k0 + kk);
            h0 = fmaf(zreg[q], wv.x, h0);
            h1 = fmaf(zreg[q], wv.y, h1);
            h2 = fmaf(zreg[q], wv.z, h2);
            h3 = fmaf(zreg[q], wv.w, h3);
        }
        float4 o;
        o.x = to_tf32(fmaxf(h0, 0.0f));
        o.y = to_tf32(fmaxf(h1, 0.0f));
        o.z = to_tf32(fmaxf(h2, 0.0f));
        o.w = to_tf32(fmaxf(h3, 0.0f));
        *(float4*)(hs + hm * 132 + kk) = o;
    }
    __syncthreads();

    // permute-write: 2048 float4s per tile, 8 per thread, coalesced STG
    #pragma unroll
    for (int r = 0; r < 8; r++) {
        const int j    = tid + r * 256;
        const int lane = j & 31;
        const int mt   = (j >> 5) & 1;
        const int ks   = (j >> 6) & 3;
        const int cc   = (j >> 8) & 3;    // chunk within tile (128 k = 4 chunks)
        const int m32  = (j >> 10) & 1;
        const int g    = lane >> 2;
        const int t    = lane & 3;
        const int r0   = m32 * 32 + mt * 16 + g;
        const int kk   = cc * 32 + ks * 8 + t;
        float4 v;
        v.x = hs[r0 * 132 + kk];
        v.y = hs[(r0 + 8) * 132 + kk];
        v.z = hs[r0 * 132 + kk + 4];
        v.w = hs[(r0 + 8) * 132 + kk + 4];
        const int m32g = blockIdx.x * 2 + m32;
        const int cg   = blockIdx.y * 4 + cc;
        ((float4*)g_HP)[((size_t)(m32g * 64 + cg) * 8 + ks * 2 + mt) * 32 + lane] = v;
    }
}

// ---------------- main kernel: pure streamed tf32 GEMM ----------------
__global__ __launch_bounds__(NTH, 2)
void ffq_mma_kernel(const float* __restrict__ b2, float* __restrict__ out) {
    extern __shared__ float smf[];
    float* bbuf = smf;                 // [2][BCH_F]
    const uint32_t sb_b = smem_u32(bbuf);

    const int tid = threadIdx.x;
    const int w   = tid >> 5;
    const int l   = tid & 31;
    const int m0  = blockIdx.x * BM;
    const int n0  = blockIdx.y * BN;

    // warp tile: 2 (m) x 4 (n); WM=32, WN=64
    const int wm  = (w & 1) * 32;
    const int wn  = (w >> 1) * 64;
    const int wnb = w >> 1;
    const int m32blk = blockIdx.x * 2 + (w & 1);

    const int g = l >> 2;
    const int t = l & 3;

    const float*  w2pc = g_W2P + (size_t)blockIdx.y * BCH_F;   // + c*2*BCH_F per chunk
    const float4* HP4  = (const float4*)g_HP;
    // per-warp A base: float4 index ((m32blk*64 + c)*8 + ks*2 + mt)*32 + l
    const float4* ap0  = HP4 + ((size_t)m32blk * 64) * 256 + l;

    // ---- prologue: cp.async chunk 0 -> buf0 ----
    {
        #pragma unroll
        for (int i = 0; i < 8; i++)
            cp16(sb_b + (uint32_t)(i * 256 + tid) * 16u,
                 w2pc + (size_t)(i * 256 + tid) * 4);
        CP_COMMIT();
    }

    float acc[2][8][4];
    #pragma unroll
    for (int mt = 0; mt < 2; mt++)
        #pragma unroll
        for (int nt = 0; nt < 8; nt++)
            #pragma unroll
            for (int v = 0; v < 4; v++) acc[mt][nt][v] = 0.0f;

    for (int c = 0; c < NCHUNK; c++) {
        const int rb = c & 1;

        CP_WAIT0();
        __syncthreads();     // cp(c) visible; prior-buffer reads done

        // ---- cp.async chunk c+1 into other B buffer ----
        if (c + 1 < NCHUNK) {
            const uint32_t dstb = sb_b + (uint32_t)(rb ^ 1) * (BCH_F * 4u);
            const float* src = w2pc + (size_t)(c + 1) * 2 * BCH_F;
            #pragma unroll
            for (int i = 0; i < 8; i++)
                cp16(dstb + (uint32_t)(i * 256 + tid) * 16u,
                     src + (size_t)(i * 256 + tid) * 4);
            CP_COMMIT();
        }

        // ---- MMA(c): A from gmem (L1-cached, x4 warp reuse), B from smem ----
        const float4* bch = (const float4*)(bbuf + rb * BCH_F);
        const float4* apc = ap0 + (size_t)c * 256;
        #pragma unroll
        for (int ks = 0; ks < 4; ks++) {
            // A fragments: 2x LDG.128, lane-consecutive (coalesced)
            const float4 av0 = apc[ks * 64];          // mt = 0
            const float4 av1 = apc[ks * 64 + 32];     // mt = 1
            uint32_t a[2][4];
            a[0][0] = __float_as_uint(av0.x); a[0][1] = __float_as_uint(av0.y);
            a[0][2] = __float_as_uint(av0.z); a[0][3] = __float_as_uint(av0.w);
            a[1][0] = __float_as_uint(av1.x); a[1][1] = __float_as_uint(av1.y);
            a[1][2] = __float_as_uint(av1.z); a[1][3] = __float_as_uint(av1.w);

            // B fragments: 4x LDS.128, lane-major, conflict-free
            const float4* blk = bch + (size_t)((wnb * 4 + ks) * 4) * 32 + l;
            const float4 lg0 = blk[0];
            const float4 lg1 = blk[32];
            const float4 lg2 = blk[64];
            const float4 lg3 = blk[96];
            uint32_t bf[8][2];
            bf[0][0] = __float_as_uint(lg0.x); bf[1][0] = __float_as_uint(lg0.y);
            bf[2][0] = __float_as_uint(lg0.z); bf[3][0] = __float_as_uint(lg0.w);
            bf[4][0] = __float_as_uint(lg1.x); bf[5][0] = __float_as_uint(lg1.y);
            bf[6][0] = __float_as_uint(lg1.z); bf[7][0] = __float_as_uint(lg1.w);
            bf[0][1] = __float_as_uint(lg2.x); bf[1][1] = __float_as_uint(lg2.y);
            bf[2][1] = __float_as_uint(lg2.z); bf[3][1] = __float_as_uint(lg2.w);
            bf[4][1] = __float_as_uint(lg3.x); bf[5][1] = __float_as_uint(lg3.y);
            bf[6][1] = __float_as_uint(lg3.z); bf[7][1] = __float_as_uint(lg3.w);

            #pragma unroll
            for (int mt = 0; mt < 2; mt++)
                #pragma unroll
                for (int nt = 0; nt < 8; nt++)
                    mma8(acc[mt][nt], a[mt], bf[nt]);
        }
    }

    // ---- epilogue: add b2, store ----
    {
        #pragma unroll
        for (int nt = 0; nt < 8; nt++) {
            const int col = n0 + wn + nt * 8 + t * 2;
            const float2 bb = *(const float2*)(b2 + col);
            #pragma unroll
            for (int mt = 0; mt < 2; mt++) {
                const int r0 = m0 + wm + mt * 16 + g;
                float2 v0, v1;
                v0.x = acc[mt][nt][0] + bb.x;
                v0.y = acc[mt][nt][1] + bb.y;
                v1.x = acc[mt][nt][2] + bb.x;
                v1.y = acc[mt][nt][3] + bb.y;
                *(float2*)(out + (size_t)r0 * E_ + col)       = v0;
                *(float2*)(out + (size_t)(r0 + 8) * E_ + col) = v1;
            }
        }
    }
}

extern "C" void kernel_launch(void* const* d_in, const int* in_sizes, int n_in,
                              void* d_out, int out_size) {
    // Identify inputs by element count (order-proof; all sizes distinct)
    const float *x = nullptr, *theta = nullptr, *W1 = nullptr,
                *b1 = nullptr, *W2 = nullptr, *b2 = nullptr;
    for (int i = 0; i < n_in; i++) {
        switch (in_sizes[i]) {
            case B_ * S_ * E_: x     = (const float*)d_in[i]; break;
            case F_ * E_:      W2    = (const float*)d_in[i]; break;
            case Q_ * F_:      W1    = (const float*)d_in[i]; break;
            case F_:           b1    = (const float*)d_in[i]; break;
            case E_:           b2    = (const float*)d_in[i]; break;
            case Q_:           theta = (const float*)d_in[i]; break;
            default: break;
        }
    }
    float* out = (float*)d_out;

    cudaFuncSetAttribute(ffq_mma_kernel,
                         cudaFuncAttributeMaxDynamicSharedMemorySize,
                         SMEM_TOTAL_BYTES);

    // prepass 1: W2 -> fragment order (tf32)
    w2_permute_kernel<<<(F_ * E_) / 256, 256>>>(W2);
    // prepass 2: H = relu(z@W1+b1) -> fragment order (tf32)
    h_permute_kernel<<<dim3(M_ / 64, F_ / 128), 256>>>(x, theta, W1, b1);

    // main: pure streamed GEMM
    dim3 grid(M_ / BM, E_ / BN);   // 128 x 2 = 256 CTAs
    ffq_mma_kernel<<<grid, NTH, SMEM_TOTAL_BYTES>>>(b2, out);
}

// round 13
// speedup vs baseline: 1.0946x; 1.0946x over previous
#include <cuda_runtime.h>
#include <cstdint>

// Problem constants
#define B_  4
#define S_  2048
#define E_  512
#define Q_  8
#define F_  2048
#define M_  (B_ * S_)

// Tiling
#define BM 64
#define BN 256
#define NTH 256
#define NCHUNK (F_ / 32)      // 64

// ---- persistent scratch ----
// W2 permuted into lane-major B-fragment order, tf32-pre-rounded:
//   float4 index: (c*2 + n0blk)*2048 + ((wnb*4 + ks)*4 + f)*32 + lane
__device__ float g_W2P[(size_t)F_ * E_];
// H = relu(z@W1 + b1), tf32-rounded, A-fragment lane-major order:
//   float4 index: ((m32blk*64 + c)*8 + ks*2 + mt)*32 + lane
__device__ float g_HP[(size_t)M_ * F_];    // 67 MB

// ---------------- helpers ----------------
__device__ __forceinline__ float to_tf32(float f) {
    uint32_t r;
    asm("cvt.rna.tf32.f32 %0, %1;" : "=r"(r) : "f"(f));
    return __uint_as_float(r);
}

// D(16x8,f32) += A(16x8,tf32 row) * B(8x8,tf32 col)
__device__ __forceinline__ void mma8(float* d, const uint32_t* a, const uint32_t* b) {
    asm volatile(
        "mma.sync.aligned.m16n8k8.row.col.f32.tf32.tf32.f32 "
        "{%0,%1,%2,%3}, {%4,%5,%6,%7}, {%8,%9}, {%0,%1,%2,%3};"
        : "+f"(d[0]), "+f"(d[1]), "+f"(d[2]), "+f"(d[3])
        : "r"(a[0]), "r"(a[1]), "r"(a[2]), "r"(a[3]), "r"(b[0]), "r"(b[1]));
}

// ---------------- prepass 1: permute + tf32-round W2 into g_W2P ----------------
__global__ void w2_permute_kernel(const float* __restrict__ W2) {
    const int idx = blockIdx.x * 256 + threadIdx.x;     // 0 .. F_*E_-1
    const int k = idx >> 9;
    const int n = idx & (E_ - 1);

    const int c   = k >> 5;
    const int kk  = k & 31;
    const int ks  = kk >> 3;
    const int r8  = kk & 7;
    const int t   = r8 & 3;
    const int rh  = r8 >> 2;

    const int n0blk = n >> 8;
    const int n256  = n & 255;
    const int wnb   = n256 >> 6;
    const int n64   = n256 & 63;
    const int g     = n64 & 7;
    const int nt    = n64 >> 3;

    const int f    = rh * 2 + (nt >> 2);
    const int elem = nt & 3;
    const int lane = g * 4 + t;

    const size_t f4idx = (size_t)(((wnb * 4 + ks) * 4 + f) * 32 + lane);
    const size_t dst = ((size_t)c * 2 + n0blk) * 8192 + f4idx * 4 + elem;
    g_W2P[dst] = to_tf32(W2[(size_t)k * E_ + n]);
}

// ---------------- prepass 2: compute H + permute into g_HP ----------------
// grid (M_/64, F_/128), block 256. Tile: 64 rows x 128 k.
__global__ __launch_bounds__(256) void h_permute_kernel(
    const float* __restrict__ x, const float* __restrict__ theta,
    const float* __restrict__ W1, const float* __restrict__ b1) {
    __shared__ float hs[64 * 132];
    const int tid = threadIdx.x;
    const int m0  = blockIdx.x * 64;
    const int k0  = blockIdx.y * 128;
    const int hm  = tid & 63;
    const int kq  = tid >> 6;

    float zreg[Q_];
    {
        const float4 x0 = *(const float4*)(x + (size_t)(m0 + hm) * E_);
        const float4 x1 = *(const float4*)(x + (size_t)(m0 + hm) * E_ + 4);
        zreg[0] = cosf(theta[0]) * cosf(x0.x);
        zreg[1] = cosf(theta[1]) * cosf(x0.y);
        zreg[2] = cosf(theta[2]) * cosf(x0.z);
        zreg[3] = cosf(theta[3]) * cosf(x0.w);
        zreg[4] = cosf(theta[4]) * cosf(x1.x);
        zreg[5] = cosf(theta[5]) * cosf(x1.y);
        zreg[6] = cosf(theta[6]) * cosf(x1.z);
        zreg[7] = cosf(theta[7]) * cosf(x1.w);
    }

    #pragma unroll
    for (int c2 = 0; c2 < 8; c2++) {
        const int kk = kq * 32 + c2 * 4;
        const float4 b1v = *(const float4*)(b1 + k0 + kk);
        float h0 = b1v.x, h1 = b1v.y, h2 = b1v.z, h3 = b1v.w;
        #pragma unroll
        for (int q = 0; q < Q_; q++) {
            const float4 wv = *(const float4*)(W1 + (size_t)q * F_ + k0 + kk);
            h0 = fmaf(zreg[q], wv.x, h0);
            h1 = fmaf(zreg[q], wv.y, h1);
            h2 = fmaf(zreg[q], wv.z, h2);
            h3 = fmaf(zreg[q], wv.w, h3);
        }
        float4 o;
        o.x = to_tf32(fmaxf(h0, 0.0f));
        o.y = to_tf32(fmaxf(h1, 0.0f));
        o.z = to_tf32(fmaxf(h2, 0.0f));
        o.w = to_tf32(fmaxf(h3, 0.0f));
        *(float4*)(hs + hm * 132 + kk) = o;
    }
    __syncthreads();

    #pragma unroll
    for (int r = 0; r < 8; r++) {
        const int j    = tid + r * 256;
        const int lane = j & 31;
        const int mt   = (j >> 5) & 1;
        const int ks   = (j >> 6) & 3;
        const int cc   = (j >> 8) & 3;
        const int m32  = (j >> 10) & 1;
        const int g    = lane >> 2;
        const int t    = lane & 3;
        const int r0   = m32 * 32 + mt * 16 + g;
        const int kk   = cc * 32 + ks * 8 + t;
        float4 v;
        v.x = hs[r0 * 132 + kk];
        v.y = hs[(r0 + 8) * 132 + kk];
        v.z = hs[r0 * 132 + kk + 4];
        v.w = hs[(r0 + 8) * 132 + kk + 4];
        const int m32g = blockIdx.x * 2 + m32;
        const int cg   = blockIdx.y * 4 + cc;
        ((float4*)g_HP)[((size_t)(m32g * 64 + cg) * 8 + ks * 2 + mt) * 32 + lane] = v;
    }
}

// ---------------- main kernel: barrier-free gmem-fed tf32 GEMM ----------------
// No smem, no __syncthreads in the mainloop: operands stream via LDG.128 from
// fragment-ordered gmem (W2P L2-resident, H L2-mostly-resident), 1-step
// software pipeline across ks.
__global__ __launch_bounds__(NTH, 2)
void ffq_mma_kernel(const float* __restrict__ b2, float* __restrict__ out) {
    const int tid = threadIdx.x;
    const int w   = tid >> 5;
    const int l   = tid & 31;
    const int m0  = blockIdx.x * BM;
    const int n0  = blockIdx.y * BN;

    // warp tile: 2 (m) x 4 (n); WM=32, WN=64
    const int wm  = (w & 1) * 32;
    const int wn  = (w >> 1) * 64;
    const int wnb = w >> 1;
    const int m32blk = blockIdx.x * 2 + (w & 1);

    const int g = l >> 2;
    const int t = l & 3;

    // A: float4 base; per chunk +256, per ks +64, mt -> +0/+32
    const float4* Ab = (const float4*)g_HP + (size_t)m32blk * 16384 + l;
    // B: float4 base; per chunk +4096, per ks +128, f -> +0/+32/+64/+96
    const float4* Bb = (const float4*)g_W2P + (size_t)blockIdx.y * 2048
                     + (size_t)wnb * 512 + l;

    float acc[2][8][4];
    #pragma unroll
    for (int mt = 0; mt < 2; mt++)
        #pragma unroll
        for (int nt = 0; nt < 8; nt++)
            #pragma unroll
            for (int v = 0; v < 4; v++) acc[mt][nt][v] = 0.0f;

    // ---- prime the pipeline with (c=0, ks=0) ----
    float4 av0 = Ab[0];
    float4 av1 = Ab[32];
    float4 lg0 = Bb[0];
    float4 lg1 = Bb[32];
    float4 lg2 = Bb[64];
    float4 lg3 = Bb[96];

    for (int c = 0; c < NCHUNK; c++) {
        #pragma unroll
        for (int ks = 0; ks < 4; ks++) {
            // snapshot current fragments (SSA renames, no movs after unroll)
            const float4 cav0 = av0, cav1 = av1;
            const float4 cg0 = lg0, cg1 = lg1, cg2 = lg2, cg3 = lg3;

            // prefetch next (c, ks+1) / (c+1, 0)
            const int last = (c == NCHUNK - 1) && (ks == 3);
            if (!last) {
                const int nc  = (ks == 3) ? c + 1 : c;
                const int nks = (ks + 1) & 3;
                const float4* An = Ab + (size_t)nc * 256 + nks * 64;
                const float4* Bn = Bb + (size_t)nc * 4096 + nks * 128;
                av0 = An[0];
                av1 = An[32];
                lg0 = Bn[0];
                lg1 = Bn[32];
                lg2 = Bn[64];
                lg3 = Bn[96];
            }

            // unpack + 16 HMMA on current fragments
            uint32_t a[2][4];
            a[0][0] = __float_as_uint(cav0.x); a[0][1] = __float_as_uint(cav0.y);
            a[0][2] = __float_as_uint(cav0.z); a[0][3] = __float_as_uint(cav0.w);
            a[1][0] = __float_as_uint(cav1.x); a[1][1] = __float_as_uint(cav1.y);
            a[1][2] = __float_as_uint(cav1.z); a[1][3] = __float_as_uint(cav1.w);
            uint32_t bf[8][2];
            bf[0][0] = __float_as_uint(cg0.x); bf[1][0] = __float_as_uint(cg0.y);
            bf[2][0] = __float_as_uint(cg0.z); bf[3][0] = __float_as_uint(cg0.w);
            bf[4][0] = __float_as_uint(cg1.x); bf[5][0] = __float_as_uint(cg1.y);
            bf[6][0] = __float_as_uint(cg1.z); bf[7][0] = __float_as_uint(cg1.w);
            bf[0][1] = __float_as_uint(cg2.x); bf[1][1] = __float_as_uint(cg2.y);
            bf[2][1] = __float_as_uint(cg2.z); bf[3][1] = __float_as_uint(cg2.w);
            bf[4][1] = __float_as_uint(cg3.x); bf[5][1] = __float_as_uint(cg3.y);
            bf[6][1] = __float_as_uint(cg3.z); bf[7][1] = __float_as_uint(cg3.w);

            #pragma unroll
            for (int mt = 0; mt < 2; mt++)
                #pragma unroll
                for (int nt = 0; nt < 8; nt++)
                    mma8(acc[mt][nt], a[mt], bf[nt]);
        }
    }

    // ---- epilogue: add b2, store ----
    {
        #pragma unroll
        for (int nt = 0; nt < 8; nt++) {
            const int col = n0 + wn + nt * 8 + t * 2;
            const float2 bb = *(const float2*)(b2 + col);
            #pragma unroll
            for (int mt = 0; mt < 2; mt++) {
                const int r0 = m0 + wm + mt * 16 + g;
                float2 v0, v1;
                v0.x = acc[mt][nt][0] + bb.x;
                v0.y = acc[mt][nt][1] + bb.y;
                v1.x = acc[mt][nt][2] + bb.x;
                v1.y = acc[mt][nt][3] + bb.y;
                *(float2*)(out + (size_t)r0 * E_ + col)       = v0;
                *(float2*)(out + (size_t)(r0 + 8) * E_ + col) = v1;
            }
        }
    }
}

extern "C" void kernel_launch(void* const* d_in, const int* in_sizes, int n_in,
                              void* d_out, int out_size) {
    // Identify inputs by element count (order-proof; all sizes distinct)
    const float *x = nullptr, *theta = nullptr, *W1 = nullptr,
                *b1 = nullptr, *W2 = nullptr, *b2 = nullptr;
    for (int i = 0; i < n_in; i++) {
        switch (in_sizes[i]) {
            case B_ * S_ * E_: x     = (const float*)d_in[i]; break;
            case F_ * E_:      W2    = (const float*)d_in[i]; break;
            case Q_ * F_:      W1    = (const float*)d_in[i]; break;
            case F_:           b1    = (const float*)d_in[i]; break;
            case E_:           b2    = (const float*)d_in[i]; break;
            case Q_:           theta = (const float*)d_in[i]; break;
            default: break;
        }
    }
    float* out = (float*)d_out;

    // prepass 1: W2 -> fragment order (tf32)
    w2_permute_kernel<<<(F_ * E_) / 256, 256>>>(W2);
    // prepass 2: H = relu(z@W1+b1) -> fragment order (tf32)
    h_permute_kernel<<<dim3(M_ / 64, F_ / 128), 256>>>(x, theta, W1, b1);

    // main: barrier-free streamed GEMM
    dim3 grid(M_ / BM, E_ / BN);   // 128 x 2 = 256 CTAs, 2 CTAs/SM
    ffq_mma_kernel<<<grid, NTH>>>(b2, out);
}

// round 14
// speedup vs baseline: 1.7081x; 1.5605x over previous
#include <cuda_runtime.h>
#include <cuda_fp16.h>
#include <cstdint>

// Problem constants
#define B_  4
#define S_  2048
#define E_  512
#define Q_  8
#define F_  2048
#define M_  (B_ * S_)

// Tiling
#define BM 64
#define BN 256
#define NTH 256
#define NCHUNK (F_ / 32)      // 64

// ---- persistent scratch (fp16 packed as b32 pairs) ----
// W2P: B-fragment lane-major fp16. uint4 index:
//   (c*2 + n0blk)*1024 + (wnb*2 + ks)*128 + f*32 + lane
//   u[f].comp[e]: f = r*2 + (nt>>2), e = nt&3; b-reg r: k = c*32+ks*16+r*8+2t(+1), n = n0blk*256+wnb*64+nt*8+g
__device__ uint32_t g_W2P[(size_t)F_ * E_ / 2];    // 2 MB
// HP: A-fragment lane-major fp16. uint4 index:
//   (m32blk*64 + c)*4*32 + (ks*2 + mt)*32 + lane
//   comp r: row = m32blk*32 + mt*16 + g + (r&1)*8, k = c*32+ks*16+(r>>1)*8+2t(+1)
__device__ uint32_t g_HP[(size_t)M_ * F_ / 2];     // 32 MB

// ---------------- helpers ----------------
__device__ __forceinline__ uint32_t pack_h2(float lo, float hi) {
    __half2 h = __floats2half2_rn(lo, hi);
    return *reinterpret_cast<uint32_t*>(&h);
}

// D(16x8,f32) += A(16x16,f16 row) * B(16x8,f16 col)
__device__ __forceinline__ void mma16(float* d, const uint32_t* a, const uint32_t* b) {
    asm volatile(
        "mma.sync.aligned.m16n8k16.row.col.f32.f16.f16.f32 "
        "{%0,%1,%2,%3}, {%4,%5,%6,%7}, {%8,%9}, {%0,%1,%2,%3};"
        : "+f"(d[0]), "+f"(d[1]), "+f"(d[2]), "+f"(d[3])
        : "r"(a[0]), "r"(a[1]), "r"(a[2]), "r"(a[3]), "r"(b[0]), "r"(b[1]));
}

// ---------------- prepass 1: W2 -> fp16 B-fragment order ----------------
// One thread per output b32 (k-pair). 524288 threads.
__global__ void w2_permute_kernel(const float* __restrict__ W2) {
    const int idx = blockIdx.x * 256 + threadIdx.x;    // 0 .. 2^19-1
    const int e     = idx & 3;
    const int lane  = (idx >> 2) & 31;
    const int f     = (idx >> 7) & 3;
    const int ks    = (idx >> 9) & 1;
    const int wnb   = (idx >> 10) & 3;
    const int n0blk = (idx >> 12) & 1;
    const int c     = idx >> 13;

    const int r  = f >> 1;
    const int nt = (f & 1) * 4 + e;
    const int g  = lane >> 2;
    const int t  = lane & 3;

    const int n = n0blk * 256 + wnb * 64 + nt * 8 + g;
    const int k = c * 32 + ks * 16 + r * 8 + 2 * t;

    g_W2P[idx] = pack_h2(W2[(size_t)k * E_ + n], W2[(size_t)(k + 1) * E_ + n]);
}

// ---------------- prepass 2: H = relu(z@W1+b1) -> fp16 A-fragment order ----------------
// grid (M_/64, F_/128), block 256. Tile 64 rows x 128 k.
__global__ __launch_bounds__(256) void h_permute_kernel(
    const float* __restrict__ x, const float* __restrict__ theta,
    const float* __restrict__ W1, const float* __restrict__ b1) {
    __shared__ float hs[64 * 132];
    const int tid = threadIdx.x;
    const int m0  = blockIdx.x * 64;
    const int k0  = blockIdx.y * 128;
    const int hm  = tid & 63;
    const int kq  = tid >> 6;

    float zreg[Q_];
    {
        const float4 x0 = *(const float4*)(x + (size_t)(m0 + hm) * E_);
        const float4 x1 = *(const float4*)(x + (size_t)(m0 + hm) * E_ + 4);
        zreg[0] = cosf(theta[0]) * cosf(x0.x);
        zreg[1] = cosf(theta[1]) * cosf(x0.y);
        zreg[2] = cosf(theta[2]) * cosf(x0.z);
        zreg[3] = cosf(theta[3]) * cosf(x0.w);
        zreg[4] = cosf(theta[4]) * cosf(x1.x);
        zreg[5] = cosf(theta[5]) * cosf(x1.y);
        zreg[6] = cosf(theta[6]) * cosf(x1.z);
        zreg[7] = cosf(theta[7]) * cosf(x1.w);
    }

    #pragma unroll
    for (int c2 = 0; c2 < 8; c2++) {
        const int kk = kq * 32 + c2 * 4;
        const float4 b1v = *(const float4*)(b1 + k0 + kk);
        float h0 = b1v.x, h1 = b1v.y, h2 = b1v.z, h3 = b1v.w;
        #pragma unroll
        for (int q = 0; q < Q_; q++) {
            const float4 wv = *(const float4*)(W1 + (size_t)q * F_ + k0 + kk);
            h0 = fmaf(zreg[q], wv.x, h0);
            h1 = fmaf(zreg[q], wv.y, h1);
            h2 = fmaf(zreg[q], wv.z, h2);
            h3 = fmaf(zreg[q], wv.w, h3);
        }
        float4 o;
        o.x = fmaxf(h0, 0.0f);
        o.y = fmaxf(h1, 0.0f);
        o.z = fmaxf(h2, 0.0f);
        o.w = fmaxf(h3, 0.0f);
        *(float4*)(hs + hm * 132 + kk) = o;
    }
    __syncthreads();

    // permute-write: 1024 uint4 per tile, 4 per thread, coalesced STG.128
    uint4* HP4 = (uint4*)g_HP;
    #pragma unroll
    for (int rr = 0; rr < 4; rr++) {
        const int j    = tid + rr * 256;
        const int lane = j & 31;
        const int mt   = (j >> 5) & 1;
        const int ks   = (j >> 6) & 1;
        const int cc   = (j >> 7) & 3;
        const int m32  = (j >> 9) & 1;
        const int g    = lane >> 2;
        const int t    = lane & 3;

        uint4 v;
        uint32_t* vr = (uint32_t*)&v;
        #pragma unroll
        for (int r = 0; r < 4; r++) {
            const int row = m32 * 32 + mt * 16 + g + (r & 1) * 8;
            const int kk  = cc * 32 + ks * 16 + (r >> 1) * 8 + 2 * t;
            vr[r] = pack_h2(hs[row * 132 + kk], hs[row * 132 + kk + 1]);
        }
        const int m32g = blockIdx.x * 2 + m32;
        const int cg   = blockIdx.y * 4 + cc;
        HP4[(size_t)(m32g * 64 + cg) * 128 + (ks * 2 + mt) * 32 + lane] = v;
    }
}

// ---------------- main kernel: barrier-free gmem-fed fp16 GEMM ----------------
__global__ __launch_bounds__(NTH, 2)
void ffq_mma_kernel(const float* __restrict__ b2, float* __restrict__ out) {
    const int tid = threadIdx.x;
    const int w   = tid >> 5;
    const int l   = tid & 31;
    const int m0  = blockIdx.x * BM;
    const int n0  = blockIdx.y * BN;

    // warp tile: 2 (m) x 4 (n); WM=32, WN=64
    const int wm  = (w & 1) * 32;
    const int wn  = (w >> 1) * 64;
    const int wnb = w >> 1;
    const int m32blk = blockIdx.x * 2 + (w & 1);

    const int g = l >> 2;
    const int t = l & 3;

    // A: uint4 base; per chunk +128, per (ks,mt) +(ks*2+mt)*32
    const uint4* Ab = (const uint4*)g_HP + (size_t)m32blk * 8192 + l;
    // B: uint4 base; per chunk +2048, per ks +128, per f +32
    const uint4* Bb = (const uint4*)g_W2P + (size_t)blockIdx.y * 1024
                    + (size_t)wnb * 256 + l;

    float acc[2][8][4];
    #pragma unroll
    for (int mt = 0; mt < 2; mt++)
        #pragma unroll
        for (int nt = 0; nt < 8; nt++)
            #pragma unroll
            for (int v = 0; v < 4; v++) acc[mt][nt][v] = 0.0f;

    // ---- prime pipeline with (c=0, ks=0) ----
    uint4 av0 = Ab[0];
    uint4 av1 = Ab[32];
    uint4 q0 = Bb[0];
    uint4 q1 = Bb[32];
    uint4 q2 = Bb[64];
    uint4 q3 = Bb[96];

    for (int c = 0; c < NCHUNK; c++) {
        #pragma unroll
        for (int ks = 0; ks < 2; ks++) {
            const uint4 cav0 = av0, cav1 = av1;
            const uint4 cq0 = q0, cq1 = q1, cq2 = q2, cq3 = q3;

            // prefetch next (c, ks+1) / (c+1, 0)
            const int last = (c == NCHUNK - 1) && (ks == 1);
            if (!last) {
                const int nc  = (ks == 1) ? c + 1 : c;
                const int nks = ks ^ 1;
                const uint4* An = Ab + (size_t)nc * 128 + nks * 64;
                const uint4* Bn = Bb + (size_t)nc * 2048 + nks * 128;
                av0 = An[0];
                av1 = An[32];
                q0 = Bn[0];
                q1 = Bn[32];
                q2 = Bn[64];
                q3 = Bn[96];
            }

            // A regs
            uint32_t a[2][4];
            a[0][0] = cav0.x; a[0][1] = cav0.y; a[0][2] = cav0.z; a[0][3] = cav0.w;
            a[1][0] = cav1.x; a[1][1] = cav1.y; a[1][2] = cav1.z; a[1][3] = cav1.w;
            // B regs: bf[nt][r]; r=0 -> q0/q1, r=1 -> q2/q3 (f = r*2 + (nt>>2))
            uint32_t bf[8][2];
            bf[0][0] = cq0.x; bf[1][0] = cq0.y; bf[2][0] = cq0.z; bf[3][0] = cq0.w;
            bf[4][0] = cq1.x; bf[5][0] = cq1.y; bf[6][0] = cq1.z; bf[7][0] = cq1.w;
            bf[0][1] = cq2.x; bf[1][1] = cq2.y; bf[2][1] = cq2.z; bf[3][1] = cq2.w;
            bf[4][1] = cq3.x; bf[5][1] = cq3.y; bf[6][1] = cq3.z; bf[7][1] = cq3.w;

            #pragma unroll
            for (int mt = 0; mt < 2; mt++)
                #pragma unroll
                for (int nt = 0; nt < 8; nt++)
                    mma16(acc[mt][nt], a[mt], bf[nt]);
        }
    }

    // ---- epilogue: add b2, store ----
    {
        #pragma unroll
        for (int nt = 0; nt < 8; nt++) {
            const int col = n0 + wn + nt * 8 + t * 2;
            const float2 bb = *(const float2*)(b2 + col);
            #pragma unroll
            for (int mt = 0; mt < 2; mt++) {
                const int r0 = m0 + wm + mt * 16 + g;
                float2 v0, v1;
                v0.x = acc[mt][nt][0] + bb.x;
                v0.y = acc[mt][nt][1] + bb.y;
                v1.x = acc[mt][nt][2] + bb.x;
                v1.y = acc[mt][nt][3] + bb.y;
                *(float2*)(out + (size_t)r0 * E_ + col)       = v0;
                *(float2*)(out + (size_t)(r0 + 8) * E_ + col) = v1;
            }
        }
    }
}

extern "C" void kernel_launch(void* const* d_in, const int* in_sizes, int n_in,
                              void* d_out, int out_size) {
    // Identify inputs by element count (order-proof; all sizes distinct)
    const float *x = nullptr, *theta = nullptr, *W1 = nullptr,
                *b1 = nullptr, *W2 = nullptr, *b2 = nullptr;
    for (int i = 0; i < n_in; i++) {
        switch (in_sizes[i]) {
            case B_ * S_ * E_: x     = (const float*)d_in[i]; break;
            case F_ * E_:      W2    = (const float*)d_in[i]; break;
            case Q_ * F_:      W1    = (const float*)d_in[i]; break;
            case F_:           b1    = (const float*)d_in[i]; break;
            case E_:           b2    = (const float*)d_in[i]; break;
            case Q_:           theta = (const float*)d_in[i]; break;
            default: break;
        }
    }
    float* out = (float*)d_out;

    // prepass 1: W2 -> fp16 B-fragment order (2 MB, L2-resident)
    w2_permute_kernel<<<(F_ * E_ / 2) / 256, 256>>>(W2);
    // prepass 2: H -> fp16 A-fragment order (32 MB)
    h_permute_kernel<<<dim3(M_ / 64, F_ / 128), 256>>>(x, theta, W1, b1);

    // main: barrier-free streamed fp16 GEMM
    dim3 grid(M_ / BM, E_ / BN);   // 128 x 2 = 256 CTAs, 2 CTAs/SM
    ffq_mma_kernel<<<grid, NTH>>>(b2, out);
}